// round 14
// baseline (speedup 1.0000x reference)
#include <cuda_runtime.h>
#include <cuda_fp16.h>

#define BATCH 4
#define HEADS 16
#define SEQ   2048
#define DHEAD 64
#define NELEM (BATCH*HEADS*SEQ*DHEAD)      // 8388608
#define NMASK (BATCH*SEQ*SEQ)              // 16777216
#define NT    (SEQ/64)                     // 32 k-tiles
#define SSTR  72                           // smem half stride per 64-elem row
#define TILE_HALFS (64 * SSTR)             // 4608 halfs = 9216 B

#define CVT_BLOCKS  (NELEM/4/256)          // 8192
#define PACK_BLOCKS (NMASK/1024/8)         // 2048

// -------- device scratch --------
__device__ __half g_Kh[NELEM];             // K fp16
__device__ __half g_Vh[NELEM];             // V fp16
__device__ unsigned g_mbits[NMASK/32];     // 2MB bit-packed mask

#define QSCALE 0.1803368801111204f         // 0.125 * log2(e)

// -------- fused pre-pass: K/V convert + mask pack --------
__global__ void prepass_kernel(const float4* __restrict__ K,
                               const float4* __restrict__ V,
                               const int4*  __restrict__ mask)
{
    int bx = blockIdx.x;
    int tid = threadIdx.x;
    if (bx < CVT_BLOCKS) {
        int i = bx * 256 + tid;
        float4 k = K[i];
        __half2 k01 = __floats2half2_rn(k.x, k.y);
        __half2 k23 = __floats2half2_rn(k.z, k.w);
        uint2 ko = { *(unsigned*)&k01, *(unsigned*)&k23 };
        ((uint2*)g_Kh)[i] = ko;

        float4 v = V[i];
        __half2 v01 = __floats2half2_rn(v.x, v.y);
        __half2 v23 = __floats2half2_rn(v.z, v.w);
        uint2 vo = { *(unsigned*)&v01, *(unsigned*)&v23 };
        ((uint2*)g_Vh)[i] = vo;
    } else {
        int gwarp = ((bx - CVT_BLOCKS) * 256 + tid) >> 5;
        int lane = tid & 31;
        int sub = lane >> 3;
        int oct = lane & 7;
        size_t vbase = (size_t)gwarp * 256;
        #pragma unroll
        for (int i = 0; i < 8; i++) {
            int word_id = i * 4 + sub;
            int4 v = mask[vbase + (size_t)word_id * 8 + oct];
            unsigned nib = (v.x != 0 ? 1u : 0u) | (v.y != 0 ? 2u : 0u)
                         | (v.z != 0 ? 4u : 0u) | (v.w != 0 ? 8u : 0u);
            unsigned part = nib << (4 * oct);
            part |= __shfl_xor_sync(0xffffffffu, part, 1);
            part |= __shfl_xor_sync(0xffffffffu, part, 2);
            part |= __shfl_xor_sync(0xffffffffu, part, 4);
            if (oct == 0) g_mbits[gwarp * 32 + word_id] = part;
        }
    }
}

// -------- helpers --------
__device__ __forceinline__ void mma16816(float* c, const unsigned* a,
                                         unsigned b0, unsigned b1)
{
    asm volatile(
        "mma.sync.aligned.m16n8k16.row.col.f32.f16.f16.f32 "
        "{%0,%1,%2,%3}, {%4,%5,%6,%7}, {%8,%9}, {%0,%1,%2,%3};\n"
        : "+f"(c[0]), "+f"(c[1]), "+f"(c[2]), "+f"(c[3])
        : "r"(a[0]), "r"(a[1]), "r"(a[2]), "r"(a[3]), "r"(b0), "r"(b1));
}

__device__ __forceinline__ void ldsm4(unsigned* r, const void* p)
{
    unsigned a = (unsigned)__cvta_generic_to_shared(p);
    asm volatile("ldmatrix.sync.aligned.m8n8.x4.shared.b16 {%0,%1,%2,%3}, [%4];"
                 : "=r"(r[0]), "=r"(r[1]), "=r"(r[2]), "=r"(r[3]) : "r"(a));
}

__device__ __forceinline__ void ldsm4t(unsigned* r, const void* p)
{
    unsigned a = (unsigned)__cvta_generic_to_shared(p);
    asm volatile("ldmatrix.sync.aligned.m8n8.x4.trans.shared.b16 {%0,%1,%2,%3}, [%4];"
                 : "=r"(r[0]), "=r"(r[1]), "=r"(r[2]), "=r"(r[3]) : "r"(a));
}

__device__ __forceinline__ unsigned h2u(__half2 h) {
    return *reinterpret_cast<unsigned*>(&h);
}

__device__ __forceinline__ float fexp2(float x) {
    float y;
    asm("ex2.approx.ftz.f32 %0, %1;" : "=f"(y) : "f"(x));
    return y;
}

__device__ __forceinline__ void cp16(void* smem_dst, const void* gsrc)
{
    unsigned d = (unsigned)__cvta_generic_to_shared(smem_dst);
    asm volatile("cp.async.ca.shared.global [%0], [%1], 16;\n" :: "r"(d), "l"(gsrc));
}
__device__ __forceinline__ void cp_commit() {
    asm volatile("cp.async.commit_group;\n");
}
template<int N> __device__ __forceinline__ void cp_wait() {
    asm volatile("cp.async.wait_group %0;\n" :: "n"(N));
}

// -------- main attention kernel --------
__global__ __launch_bounds__(128, 4)
void flash_attn_hmma_kernel(const float* __restrict__ Q, float* __restrict__ O)
{
    extern __shared__ __align__(16) __half smbuf[];
    // ring buffer i in {0,1,2}: K tile at i*2*TILE_HALFS, V tile at +TILE_HALFS

    const int tid  = threadIdx.x;
    const int warp = tid >> 5;
    const int lane = tid & 31;
    const int bh = blockIdx.y;
    const int b  = bh >> 4;
    const int q0 = blockIdx.x * 64;

    int cr[4], cc[4];
    #pragma unroll
    for (int i = 0; i < 4; i++) {
        int idx = i * 128 + tid;
        cr[i] = idx >> 3;
        cc[i] = (idx & 7) * 8;
    }

    // ---- prologue: K/V tile0 -> buf0 ; tile1 -> buf1 ----
    {
        const size_t gb = (size_t)bh * SEQ * DHEAD;
        #pragma unroll
        for (int i = 0; i < 4; i++) {
            size_t go = gb + cr[i] * DHEAD + cc[i];
            cp16(&smbuf[cr[i] * SSTR + cc[i]], &g_Kh[go]);
            cp16(&smbuf[TILE_HALFS + cr[i] * SSTR + cc[i]], &g_Vh[go]);
        }
        cp_commit();                                  // group: T0
        #pragma unroll
        for (int i = 0; i < 4; i++) {
            size_t go = gb + (size_t)64 * DHEAD + cr[i] * DHEAD + cc[i];
            cp16(&smbuf[2 * TILE_HALFS + cr[i] * SSTR + cc[i]], &g_Kh[go]);
            cp16(&smbuf[3 * TILE_HALFS + cr[i] * SSTR + cc[i]], &g_Vh[go]);
        }
        cp_commit();                                  // group: T1
    }

    const int gr0 = q0 + warp * 16 + (lane >> 2);   // row for fragment regs a0/a2

    // ---- load Q fragments directly from fp32 global (no smem, no ldsm) ----
    // m16n8k16 A layout: {a0:(r,c..c+1), a1:(r+8,c..c+1), a2:(r,c+8..c+9), a3:(r+8,c+8..c+9)}
    unsigned qh[4][4];
    {
        const float* qrow = Q + ((size_t)bh * SEQ + gr0) * DHEAD;
        const int c0 = (lane & 3) * 2;
        #pragma unroll
        for (int kc = 0; kc < 4; kc++) {
            int c = kc * 16 + c0;
            float2 f00 = *(const float2*)&qrow[c];
            float2 f10 = *(const float2*)&qrow[8 * DHEAD + c];
            float2 f01 = *(const float2*)&qrow[c + 8];
            float2 f11 = *(const float2*)&qrow[8 * DHEAD + c + 8];
            qh[kc][0] = h2u(__floats2half2_rn(f00.x * QSCALE, f00.y * QSCALE));
            qh[kc][1] = h2u(__floats2half2_rn(f10.x * QSCALE, f10.y * QSCALE));
            qh[kc][2] = h2u(__floats2half2_rn(f01.x * QSCALE, f01.y * QSCALE));
            qh[kc][3] = h2u(__floats2half2_rn(f11.x * QSCALE, f11.y * QSCALE));
        }
    }

    float o[8][4];
    #pragma unroll
    for (int i = 0; i < 8; i++)
        #pragma unroll
        for (int j = 0; j < 4; j++) o[i][j] = 0.0f;
    float l0 = 0.0f, l1 = 0.0f;     // per-thread partial row sums

    const unsigned* mrow0 = g_mbits + (size_t)b * (SEQ * (SEQ / 32)) + (size_t)gr0 * (SEQ / 32);
    const unsigned* mrow1 = mrow0 + 8 * (SEQ / 32);
    const int bp = (lane & 3) * 2;

    #pragma unroll 1
    for (int t = 0; t < NT; t++) {
        if (t < NT - 1) cp_wait<1>(); else cp_wait<0>();
        __syncthreads();

        const __half* sK = smbuf + (t % 3) * 2 * TILE_HALFS;
        const __half* sV = sK + TILE_HALFS;

        uint2 wA = *(const uint2*)(mrow0 + (t << 1));
        uint2 wB = *(const uint2*)(mrow1 + (t << 1));

        // ---- S = Qs K^T (fp32 accum, exp2 domain) ----
        float s[8][4];
        #pragma unroll
        for (int i = 0; i < 8; i++)
            #pragma unroll
            for (int j = 0; j < 4; j++) s[i][j] = 0.0f;

        #pragma unroll
        for (int nbp = 0; nbp < 4; nbp++) {
            int krow = nbp * 16 + (lane & 15);
            int kcol = (lane >> 4) * 8;
            #pragma unroll
            for (int kc = 0; kc < 4; kc++) {
                unsigned kh[4];
                ldsm4(kh, &sK[krow * SSTR + kc * 16 + kcol]);
                mma16816(s[2 * nbp],     qh[kc], kh[0], kh[2]);
                mma16816(s[2 * nbp + 1], qh[kc], kh[1], kh[3]);
            }
        }

        // ---- prefetch tile t+2 ----
        if (t + 2 < NT) {
            __half* pK = smbuf + ((t + 2) % 3) * 2 * TILE_HALFS;
            const size_t gb = (size_t)(bh * SEQ + (t + 2) * 64) * DHEAD;
            #pragma unroll
            for (int i = 0; i < 4; i++) {
                size_t go = gb + cr[i] * DHEAD + cc[i];
                cp16(&pK[cr[i] * SSTR + cc[i]], &g_Kh[go]);
                cp16(&pK[TILE_HALFS + cr[i] * SSTR + cc[i]], &g_Vh[go]);
            }
            cp_commit();
        }

        // ---- p = exp2(s) with mask -> 0 ; accumulate l ; pack fp16 ; PV ----
        // A-fragment register order: {(b0i,row r), (b0i,row r+8), (b1i,row r), (b1i,row r+8)}
        #pragma unroll
        for (int kc2 = 0; kc2 < 4; kc2++) {
            int b0i = 2 * kc2, b1i = 2 * kc2 + 1;
            unsigned Ahi[4];
            #pragma unroll
            for (int half2i = 0; half2i < 4; half2i++) {
                int sb   = (half2i >> 1) ? b1i : b0i;   // which 8-col block
                int base = (half2i & 1) * 2;            // 0 -> row gr0 ; 2 -> row gr0+8
                unsigned wr = (base == 0)
                            ? ((sb < 4) ? wA.x : wA.y)
                            : ((sb < 4) ? wB.x : wB.y);
                int bit = (sb & 3) * 8 + bp;
                float pa = ((wr >> bit) & 1)       ? 0.0f : fexp2(s[sb][base]);
                float pb = ((wr >> (bit + 1)) & 1) ? 0.0f : fexp2(s[sb][base + 1]);
                if (base == 0) l0 += pa + pb; else l1 += pa + pb;
                Ahi[half2i] = h2u(__floats2half2_rn(pa, pb));
            }
            int vrow = kc2 * 16 + (lane & 15);
            int vcol = (lane >> 4) * 8;
            #pragma unroll
            for (int dbp = 0; dbp < 4; dbp++) {
                unsigned v[4];
                ldsm4t(v, &sV[vrow * SSTR + dbp * 16 + vcol]);
                mma16816(o[2 * dbp],     Ahi, v[0], v[1]);
                mma16816(o[2 * dbp + 1], Ahi, v[2], v[3]);
            }
        }
    }

    // ---- epilogue: single quad reduction of l, normalize, write ----
    l0 += __shfl_xor_sync(0xffffffffu, l0, 1);
    l0 += __shfl_xor_sync(0xffffffffu, l0, 2);
    l1 += __shfl_xor_sync(0xffffffffu, l1, 1);
    l1 += __shfl_xor_sync(0xffffffffu, l1, 2);
    float inv0 = 1.0f / l0, inv1 = 1.0f / l1;
    float* Op = O + (size_t)bh * SEQ * DHEAD;
    #pragma unroll
    for (int db = 0; db < 8; db++) {
        int c = db * 8 + bp;
        float2 v0 = { o[db][0] * inv0, o[db][1] * inv0 };
        float2 v1 = { o[db][2] * inv1, o[db][3] * inv1 };
        *(float2*)&Op[(size_t)gr0 * DHEAD + c]       = v0;
        *(float2*)&Op[(size_t)(gr0 + 8) * DHEAD + c] = v1;
    }
}

extern "C" void kernel_launch(void* const* d_in, const int* in_sizes, int n_in,
                              void* d_out, int out_size)
{
    const float* Q = (const float*)d_in[0];
    const float* K = (const float*)d_in[1];
    const float* V = (const float*)d_in[2];
    const int*   M = (const int*)d_in[3];
    float*       O = (float*)d_out;

    prepass_kernel<<<CVT_BLOCKS + PACK_BLOCKS, 256>>>((const float4*)K,
                                                      (const float4*)V,
                                                      (const int4*)M);

    const int smem_bytes = 3 * 2 * TILE_HALFS * (int)sizeof(__half);  // 55296
    cudaFuncSetAttribute(flash_attn_hmma_kernel,
                         cudaFuncAttributeMaxDynamicSharedMemorySize, smem_bytes);
    dim3 grid(SEQ / 64, BATCH * HEADS);
    flash_attn_hmma_kernel<<<grid, 128, smem_bytes>>>(Q, O);
}

// round 17
// speedup vs baseline: 1.2130x; 1.2130x over previous
#include <cuda_runtime.h>
#include <cuda_fp16.h>

#define BATCH 4
#define HEADS 16
#define SEQ   2048
#define DHEAD 64
#define NELEM (BATCH*HEADS*SEQ*DHEAD)      // 8388608
#define NMASK (BATCH*SEQ*SEQ)              // 16777216
#define NT    (SEQ/64)                     // 32 k-tiles
#define SSTR  72                           // smem half stride per 64-elem row
#define TILE_HALFS (64 * SSTR)             // 4608 halfs = 9216 B

#define CVT_BLOCKS  (NELEM/4/256)          // 8192
#define PACK_BLOCKS (NMASK/1024/8)         // 2048

// -------- device scratch --------
__device__ __half g_Kh[NELEM];             // K fp16
__device__ __half g_Vh[NELEM];             // V fp16
__device__ unsigned g_mbits[NMASK/32];     // 2MB bit-packed mask

#define QSCALE 0.1803368801111204f         // 0.125 * log2(e)

// -------- fused pre-pass: K/V convert + mask pack --------
__global__ void prepass_kernel(const float4* __restrict__ K,
                               const float4* __restrict__ V,
                               const int4*  __restrict__ mask)
{
    int bx = blockIdx.x;
    int tid = threadIdx.x;
    if (bx < CVT_BLOCKS) {
        int i = bx * 256 + tid;
        float4 k = K[i];
        __half2 k01 = __floats2half2_rn(k.x, k.y);
        __half2 k23 = __floats2half2_rn(k.z, k.w);
        uint2 ko = { *(unsigned*)&k01, *(unsigned*)&k23 };
        ((uint2*)g_Kh)[i] = ko;

        float4 v = V[i];
        __half2 v01 = __floats2half2_rn(v.x, v.y);
        __half2 v23 = __floats2half2_rn(v.z, v.w);
        uint2 vo = { *(unsigned*)&v01, *(unsigned*)&v23 };
        ((uint2*)g_Vh)[i] = vo;
    } else {
        int gwarp = ((bx - CVT_BLOCKS) * 256 + tid) >> 5;
        int lane = tid & 31;
        int sub = lane >> 3;
        int oct = lane & 7;
        size_t vbase = (size_t)gwarp * 256;
        #pragma unroll
        for (int i = 0; i < 8; i++) {
            int word_id = i * 4 + sub;
            int4 v = mask[vbase + (size_t)word_id * 8 + oct];
            unsigned nib = (v.x != 0 ? 1u : 0u) | (v.y != 0 ? 2u : 0u)
                         | (v.z != 0 ? 4u : 0u) | (v.w != 0 ? 8u : 0u);
            unsigned part = nib << (4 * oct);
            part |= __shfl_xor_sync(0xffffffffu, part, 1);
            part |= __shfl_xor_sync(0xffffffffu, part, 2);
            part |= __shfl_xor_sync(0xffffffffu, part, 4);
            if (oct == 0) g_mbits[gwarp * 32 + word_id] = part;
        }
    }
}

// -------- helpers --------
__device__ __forceinline__ void mma16816(float* c, const unsigned* a,
                                         unsigned b0, unsigned b1)
{
    asm volatile(
        "mma.sync.aligned.m16n8k16.row.col.f32.f16.f16.f32 "
        "{%0,%1,%2,%3}, {%4,%5,%6,%7}, {%8,%9}, {%0,%1,%2,%3};\n"
        : "+f"(c[0]), "+f"(c[1]), "+f"(c[2]), "+f"(c[3])
        : "r"(a[0]), "r"(a[1]), "r"(a[2]), "r"(a[3]), "r"(b0), "r"(b1));
}

__device__ __forceinline__ void ldsm4(unsigned* r, const void* p)
{
    unsigned a = (unsigned)__cvta_generic_to_shared(p);
    asm volatile("ldmatrix.sync.aligned.m8n8.x4.shared.b16 {%0,%1,%2,%3}, [%4];"
                 : "=r"(r[0]), "=r"(r[1]), "=r"(r[2]), "=r"(r[3]) : "r"(a));
}

__device__ __forceinline__ void ldsm4t(unsigned* r, const void* p)
{
    unsigned a = (unsigned)__cvta_generic_to_shared(p);
    asm volatile("ldmatrix.sync.aligned.m8n8.x4.trans.shared.b16 {%0,%1,%2,%3}, [%4];"
                 : "=r"(r[0]), "=r"(r[1]), "=r"(r[2]), "=r"(r[3]) : "r"(a));
}

__device__ __forceinline__ unsigned h2u(__half2 h) {
    return *reinterpret_cast<unsigned*>(&h);
}

__device__ __forceinline__ float fexp2(float x) {
    float y;
    asm("ex2.approx.ftz.f32 %0, %1;" : "=f"(y) : "f"(x));
    return y;
}

__device__ __forceinline__ void cp16(void* smem_dst, const void* gsrc)
{
    unsigned d = (unsigned)__cvta_generic_to_shared(smem_dst);
    asm volatile("cp.async.ca.shared.global [%0], [%1], 16;\n" :: "r"(d), "l"(gsrc));
}
__device__ __forceinline__ void cp_commit() {
    asm volatile("cp.async.commit_group;\n");
}
template<int N> __device__ __forceinline__ void cp_wait() {
    asm volatile("cp.async.wait_group %0;\n" :: "n"(N));
}

// -------- main attention kernel: BM=128 (4 warps x 32 Q-rows) --------
__global__ __launch_bounds__(128, 2)
void flash_attn_hmma_kernel(const float* __restrict__ Q, float* __restrict__ O)
{
    extern __shared__ __align__(16) __half smbuf[];
    // ring buffer i in {0,1,2}: K tile at i*2*TILE_HALFS, V tile at +TILE_HALFS

    const int tid  = threadIdx.x;
    const int warp = tid >> 5;
    const int lane = tid & 31;
    const int bh = blockIdx.y;
    const int b  = bh >> 4;
    const int q0 = blockIdx.x * 128;

    int cr[4], cc[4];
    #pragma unroll
    for (int i = 0; i < 4; i++) {
        int idx = i * 128 + tid;
        cr[i] = idx >> 3;
        cc[i] = (idx & 7) * 8;
    }

    // ---- prologue: K/V tile0 -> buf0 ; tile1 -> buf1 ----
    {
        const size_t gb = (size_t)bh * SEQ * DHEAD;
        #pragma unroll
        for (int i = 0; i < 4; i++) {
            size_t go = gb + cr[i] * DHEAD + cc[i];
            cp16(&smbuf[cr[i] * SSTR + cc[i]], &g_Kh[go]);
            cp16(&smbuf[TILE_HALFS + cr[i] * SSTR + cc[i]], &g_Vh[go]);
        }
        cp_commit();                                  // group: T0
        #pragma unroll
        for (int i = 0; i < 4; i++) {
            size_t go = gb + (size_t)64 * DHEAD + cr[i] * DHEAD + cc[i];
            cp16(&smbuf[2 * TILE_HALFS + cr[i] * SSTR + cc[i]], &g_Kh[go]);
            cp16(&smbuf[3 * TILE_HALFS + cr[i] * SSTR + cc[i]], &g_Vh[go]);
        }
        cp_commit();                                  // group: T1
    }

    const int grA = q0 + warp * 32 + (lane >> 2);   // block A row (regs a0/a2)
    // block B rows = grA+16 / grA+24

    // ---- Q fragments for both 16-row blocks, direct from fp32 global ----
    // m16n8k16 A layout: {a0:(r,c..c+1), a1:(r+8,..), a2:(r,c+8..), a3:(r+8,c+8..)}
    unsigned qhA[4][4], qhB[4][4];
    {
        const float* qrow = Q + ((size_t)bh * SEQ + grA) * DHEAD;
        const int c0 = (lane & 3) * 2;
        #pragma unroll
        for (int kc = 0; kc < 4; kc++) {
            int c = kc * 16 + c0;
            float2 f00 = *(const float2*)&qrow[c];
            float2 f10 = *(const float2*)&qrow[8 * DHEAD + c];
            float2 f01 = *(const float2*)&qrow[c + 8];
            float2 f11 = *(const float2*)&qrow[8 * DHEAD + c + 8];
            qhA[kc][0] = h2u(__floats2half2_rn(f00.x * QSCALE, f00.y * QSCALE));
            qhA[kc][1] = h2u(__floats2half2_rn(f10.x * QSCALE, f10.y * QSCALE));
            qhA[kc][2] = h2u(__floats2half2_rn(f01.x * QSCALE, f01.y * QSCALE));
            qhA[kc][3] = h2u(__floats2half2_rn(f11.x * QSCALE, f11.y * QSCALE));
            float2 g00 = *(const float2*)&qrow[16 * DHEAD + c];
            float2 g10 = *(const float2*)&qrow[24 * DHEAD + c];
            float2 g01 = *(const float2*)&qrow[16 * DHEAD + c + 8];
            float2 g11 = *(const float2*)&qrow[24 * DHEAD + c + 8];
            qhB[kc][0] = h2u(__floats2half2_rn(g00.x * QSCALE, g00.y * QSCALE));
            qhB[kc][1] = h2u(__floats2half2_rn(g10.x * QSCALE, g10.y * QSCALE));
            qhB[kc][2] = h2u(__floats2half2_rn(g01.x * QSCALE, g01.y * QSCALE));
            qhB[kc][3] = h2u(__floats2half2_rn(g11.x * QSCALE, g11.y * QSCALE));
        }
    }

    float oA[8][4], oB[8][4];
    #pragma unroll
    for (int i = 0; i < 8; i++)
        #pragma unroll
        for (int j = 0; j < 4; j++) { oA[i][j] = 0.0f; oB[i][j] = 0.0f; }
    float lA0 = 0.0f, lA1 = 0.0f, lB0 = 0.0f, lB1 = 0.0f;

    const size_t mstride = SEQ / 32;
    const unsigned* mbase = g_mbits + (size_t)b * SEQ * mstride;
    const unsigned* mrA0 = mbase + (size_t)grA * mstride;
    const unsigned* mrA1 = mrA0 + 8 * mstride;
    const unsigned* mrB0 = mrA0 + 16 * mstride;
    const unsigned* mrB1 = mrA0 + 24 * mstride;
    const int bp = (lane & 3) * 2;

    #pragma unroll 1
    for (int t = 0; t < NT; t++) {
        if (t < NT - 1) cp_wait<1>(); else cp_wait<0>();
        __syncthreads();

        const __half* sK = smbuf + (t % 3) * 2 * TILE_HALFS;
        const __half* sV = sK + TILE_HALFS;

        uint2 wA0 = *(const uint2*)(mrA0 + (t << 1));
        uint2 wA1 = *(const uint2*)(mrA1 + (t << 1));
        uint2 wB0 = *(const uint2*)(mrB0 + (t << 1));
        uint2 wB1 = *(const uint2*)(mrB1 + (t << 1));

        // ---- S = Qs K^T for both row-blocks (each kh feeds 4 mmas) ----
        float sA[8][4], sB[8][4];
        #pragma unroll
        for (int i = 0; i < 8; i++)
            #pragma unroll
            for (int j = 0; j < 4; j++) { sA[i][j] = 0.0f; sB[i][j] = 0.0f; }

        #pragma unroll
        for (int nbp = 0; nbp < 4; nbp++) {
            int krow = nbp * 16 + (lane & 15);
            int kcol = (lane >> 4) * 8;
            #pragma unroll
            for (int kc = 0; kc < 4; kc++) {
                unsigned kh[4];
                ldsm4(kh, &sK[krow * SSTR + kc * 16 + kcol]);
                mma16816(sA[2 * nbp],     qhA[kc], kh[0], kh[2]);
                mma16816(sA[2 * nbp + 1], qhA[kc], kh[1], kh[3]);
                mma16816(sB[2 * nbp],     qhB[kc], kh[0], kh[2]);
                mma16816(sB[2 * nbp + 1], qhB[kc], kh[1], kh[3]);
            }
        }

        // ---- prefetch tile t+2 ----
        if (t + 2 < NT) {
            __half* pK = smbuf + ((t + 2) % 3) * 2 * TILE_HALFS;
            const size_t gb = (size_t)(bh * SEQ + (t + 2) * 64) * DHEAD;
            #pragma unroll
            for (int i = 0; i < 4; i++) {
                size_t go = gb + cr[i] * DHEAD + cc[i];
                cp16(&pK[cr[i] * SSTR + cc[i]], &g_Kh[go]);
                cp16(&pK[TILE_HALFS + cr[i] * SSTR + cc[i]], &g_Vh[go]);
            }
            cp_commit();
        }

        // ---- p = exp2(s), mask->0, accumulate l, pack, PV (v reused x2) ----
        #pragma unroll
        for (int kc2 = 0; kc2 < 4; kc2++) {
            int b0i = 2 * kc2, b1i = 2 * kc2 + 1;
            unsigned AhA[4], AhB[4];
            #pragma unroll
            for (int h = 0; h < 4; h++) {
                int sb   = (h >> 1) ? b1i : b0i;
                int base = (h & 1) * 2;
                int bit = (sb & 3) * 8 + bp;
                {   // block A
                    unsigned wr = (base == 0) ? ((sb < 4) ? wA0.x : wA0.y)
                                              : ((sb < 4) ? wA1.x : wA1.y);
                    float pa = ((wr >> bit) & 1)       ? 0.0f : fexp2(sA[sb][base]);
                    float pb = ((wr >> (bit + 1)) & 1) ? 0.0f : fexp2(sA[sb][base + 1]);
                    if (base == 0) lA0 += pa + pb; else lA1 += pa + pb;
                    AhA[h] = h2u(__floats2half2_rn(pa, pb));
                }
                {   // block B
                    unsigned wr = (base == 0) ? ((sb < 4) ? wB0.x : wB0.y)
                                              : ((sb < 4) ? wB1.x : wB1.y);
                    float pa = ((wr >> bit) & 1)       ? 0.0f : fexp2(sB[sb][base]);
                    float pb = ((wr >> (bit + 1)) & 1) ? 0.0f : fexp2(sB[sb][base + 1]);
                    if (base == 0) lB0 += pa + pb; else lB1 += pa + pb;
                    AhB[h] = h2u(__floats2half2_rn(pa, pb));
                }
            }
            int vrow = kc2 * 16 + (lane & 15);
            int vcol = (lane >> 4) * 8;
            #pragma unroll
            for (int dbp = 0; dbp < 4; dbp++) {
                unsigned v[4];
                ldsm4t(v, &sV[vrow * SSTR + dbp * 16 + vcol]);
                mma16816(oA[2 * dbp],     AhA, v[0], v[1]);
                mma16816(oA[2 * dbp + 1], AhA, v[2], v[3]);
                mma16816(oB[2 * dbp],     AhB, v[0], v[1]);
                mma16816(oB[2 * dbp + 1], AhB, v[2], v[3]);
            }
        }
    }

    // ---- epilogue: quad reduction of l, normalize, write 4 row-slices ----
    lA0 += __shfl_xor_sync(0xffffffffu, lA0, 1);
    lA0 += __shfl_xor_sync(0xffffffffu, lA0, 2);
    lA1 += __shfl_xor_sync(0xffffffffu, lA1, 1);
    lA1 += __shfl_xor_sync(0xffffffffu, lA1, 2);
    lB0 += __shfl_xor_sync(0xffffffffu, lB0, 1);
    lB0 += __shfl_xor_sync(0xffffffffu, lB0, 2);
    lB1 += __shfl_xor_sync(0xffffffffu, lB1, 1);
    lB1 += __shfl_xor_sync(0xffffffffu, lB1, 2);
    float iA0 = 1.0f / lA0, iA1 = 1.0f / lA1;
    float iB0 = 1.0f / lB0, iB1 = 1.0f / lB1;
    float* Op = O + (size_t)bh * SEQ * DHEAD;
    #pragma unroll
    for (int db = 0; db < 8; db++) {
        int c = db * 8 + bp;
        float2 a0 = { oA[db][0] * iA0, oA[db][1] * iA0 };
        float2 a1 = { oA[db][2] * iA1, oA[db][3] * iA1 };
        float2 b0v = { oB[db][0] * iB0, oB[db][1] * iB0 };
        float2 b1v = { oB[db][2] * iB1, oB[db][3] * iB1 };
        *(float2*)&Op[(size_t)grA * DHEAD + c]        = a0;
        *(float2*)&Op[(size_t)(grA + 8) * DHEAD + c]  = a1;
        *(float2*)&Op[(size_t)(grA + 16) * DHEAD + c] = b0v;
        *(float2*)&Op[(size_t)(grA + 24) * DHEAD + c] = b1v;
    }
}

extern "C" void kernel_launch(void* const* d_in, const int* in_sizes, int n_in,
                              void* d_out, int out_size)
{
    const float* Q = (const float*)d_in[0];
    const float* K = (const float*)d_in[1];
    const float* V = (const float*)d_in[2];
    const int*   M = (const int*)d_in[3];
    float*       O = (float*)d_out;

    prepass_kernel<<<CVT_BLOCKS + PACK_BLOCKS, 256>>>((const float4*)K,
                                                      (const float4*)V,
                                                      (const int4*)M);

    const int smem_bytes = 3 * 2 * TILE_HALFS * (int)sizeof(__half);  // 55296
    cudaFuncSetAttribute(flash_attn_hmma_kernel,
                         cudaFuncAttributeMaxDynamicSharedMemorySize, smem_bytes);
    dim3 grid(SEQ / 128, BATCH * HEADS);   // (16, 64)
    flash_attn_hmma_kernel<<<grid, 128, smem_bytes>>>(Q, O);
}